// round 1
// baseline (speedup 1.0000x reference)
#include <cuda_runtime.h>
#include <math.h>

#define NB 32          // batch
#define INT_MIN_V ((int)0x80000000)

// scale-slot indices
#define IX_X   0
#define IX_W1  1
#define IX_W2  2
#define IX_W3  3
#define IX_FW1 4
#define IX_FW2 5
#define IX_A1  6
#define IX_A2  7
#define IX_A3  8
#define IX_F1  9

// ---------------- scratch (device globals; no allocation) ----------------
__device__ int g_maxbits[10];

__device__ __align__(16) unsigned char g_qx  [NB*784];        // (b,28,28)
__device__ __align__(16) unsigned char g_qw1 [16*25];
__device__ __align__(16) unsigned char g_qw2 [32*400];
__device__ __align__(16) unsigned char g_qw3 [64*800];
__device__ __align__(16) unsigned char g_qfw1[256*1024];
__device__ __align__(16) unsigned char g_qfw2[10*256];

__device__ float         g_act1 [NB*16*14*14];
__device__ __align__(16) unsigned char g_qact1[NB*16*14*14];
__device__ float         g_act2 [NB*32*7*7];
__device__ __align__(16) unsigned char g_qact2[NB*32*7*7];
__device__ float         g_act3 [NB*64*16];
__device__ __align__(16) unsigned char g_qact3[NB*1024];
__device__ float         g_fc1  [NB*256];
__device__ __align__(16) unsigned char g_qfc1 [NB*256];

// ---------------- helpers ----------------
__device__ __forceinline__ float scale_of(int idx) {
    // s = 255 / max(m, 1e-6), correctly-rounded division (match XLA fp32)
    float m = __int_as_float(g_maxbits[idx]);   // all maxima are >= 0
    return __fdiv_rn(255.0f, fmaxf(m, 1e-6f));
}
__device__ __forceinline__ unsigned char quant1(float v, float s) {
    float r = rintf(__fmul_rn(v, s));           // round-half-to-even == jnp.round
    r = fminf(fmaxf(r, 0.0f), 255.0f);
    return (unsigned char)(int)r;
}

// ---------------- kernels ----------------
__global__ void k_init() {
    int t = threadIdx.x;
    if (t < 10) g_maxbits[t] = 0;
}

// maxima of the 6 float inputs that get quantized
__global__ void k_max_inputs(const float* __restrict__ x,  const float* __restrict__ w1,
                             const float* __restrict__ w2, const float* __restrict__ w3,
                             const float* __restrict__ fw1,const float* __restrict__ fw2) {
    const float* src; int n; int idx = blockIdx.y;
    switch (idx) {
        case 0: src = x;   n = NB*784;   break;
        case 1: src = w1;  n = 16*25;    break;
        case 2: src = w2;  n = 32*400;   break;
        case 3: src = w3;  n = 64*800;   break;
        case 4: src = fw1; n = 256*1024; break;
        default:src = fw2; n = 10*256;   break;
    }
    float m = 0.0f;
    for (int i = blockIdx.x*blockDim.x + threadIdx.x; i < n; i += gridDim.x*blockDim.x)
        m = fmaxf(m, fabsf(src[i]));
    __shared__ int sm;
    if (threadIdx.x == 0) sm = 0;
    __syncthreads();
    atomicMax(&sm, __float_as_int(m));
    __syncthreads();
    if (threadIdx.x == 0) atomicMax(&g_maxbits[idx], sm);
}

// quantize the 6 inputs
__global__ void k_quant_inputs(const float* __restrict__ x,  const float* __restrict__ w1,
                               const float* __restrict__ w2, const float* __restrict__ w3,
                               const float* __restrict__ fw1,const float* __restrict__ fw2) {
    const float* src; unsigned char* dst; int n; int idx = blockIdx.y;
    switch (idx) {
        case 0: src = x;   dst = g_qx;   n = NB*784;   break;
        case 1: src = w1;  dst = g_qw1;  n = 16*25;    break;
        case 2: src = w2;  dst = g_qw2;  n = 32*400;   break;
        case 3: src = w3;  dst = g_qw3;  n = 64*800;   break;
        case 4: src = fw1; dst = g_qfw1; n = 256*1024; break;
        default:src = fw2; dst = g_qfw2; n = 10*256;   break;
    }
    float s = scale_of(idx);
    for (int i = blockIdx.x*blockDim.x + threadIdx.x; i < n; i += gridDim.x*blockDim.x)
        dst[i] = quant1(src[i], s);
}

// quantize activations: which = 0..3
__global__ void k_quant_act(int which) {
    const float* src; unsigned char* dst; int n; int idx;
    switch (which) {
        case 0: src = g_act1; dst = g_qact1; n = NB*16*196; idx = IX_A1; break;
        case 1: src = g_act2; dst = g_qact2; n = NB*32*49;  idx = IX_A2; break;
        case 2: src = g_act3; dst = g_qact3; n = NB*1024;   idx = IX_A3; break;
        default:src = g_fc1;  dst = g_qfc1;  n = NB*256;    idx = IX_F1; break;
    }
    float s = scale_of(idx);
    for (int i = blockIdx.x*blockDim.x + threadIdx.x; i < n; i += gridDim.x*blockDim.x)
        dst[i] = quant1(src[i], s);
}

// conv1: in (b,1,28,28) qx, w (16,25), pad 2, relu, pool2 -> act1 (b,16,14,14)
// block = (b,o), 196 threads (one per pooled output)
__global__ void k_conv1(const float* __restrict__ b1) {
    int blk = blockIdx.x; int b = blk >> 4, o = blk & 15;
    __shared__ unsigned char sa[784];
    __shared__ unsigned char sw[25];
    __shared__ int smax;
    int t = threadIdx.x;                       // 196
    for (int i = t; i < 784; i += 196) sa[i] = g_qx[b*784 + i];
    if (t < 25) sw[t] = g_qw1[o*25 + t];
    if (t == 0) smax = 0;
    __syncthreads();

    int py = t / 14, px = t % 14;
    int best = INT_MIN_V;
    #pragma unroll
    for (int dy = 0; dy < 2; dy++)
    #pragma unroll
    for (int dx = 0; dx < 2; dx++) {
        int y = 2*py + dy, x = 2*px + dx;
        int s = 0;
        #pragma unroll
        for (int ky = 0; ky < 5; ky++) {
            int iy = y + ky - 2;
            #pragma unroll
            for (int kx = 0; kx < 5; kx++) {
                int ix = x + kx - 2;
                if ((unsigned)iy < 28u && (unsigned)ix < 28u)
                    s += (sa[iy*28 + ix] * sw[ky*5 + kx]) >> 8;
            }
        }
        best = max(best, s);
    }
    float v = fmaxf((float)best + b1[o], 0.0f);
    g_act1[(b*16 + o)*196 + t] = v;
    atomicMax(&smax, __float_as_int(v));
    __syncthreads();
    if (t == 0) atomicMax(&g_maxbits[IX_A1], smax);
}

// conv2: in (b,16,14,14), w (32,400), pad 2, relu, pool2 -> act2 (b,32,7,7)
// block = (b,o), 392 threads: kc = t/196 (K halves of 200), pos = t%196 (conv position)
__global__ void k_conv2(const float* __restrict__ b2) {
    int blk = blockIdx.x; int b = blk >> 5, o = blk & 31;
    __shared__ unsigned char sa[3136];         // 16*14*14
    __shared__ unsigned char sw[400];
    __shared__ int psum[2][196];
    __shared__ int smax;
    int t = threadIdx.x;                       // 392
    for (int i = t; i < 3136; i += 392) sa[i] = g_qact1[b*3136 + i];
    for (int i = t; i < 400;  i += 392) sw[i] = g_qw2[o*400 + i];
    if (t == 0) smax = 0;
    __syncthreads();

    int kc = t / 196, pos = t % 196;
    int y = pos / 14, x = pos % 14;
    int s = 0;
    int cbase = kc * 8;                        // 200 = 8 channels * 25
    for (int c = 0; c < 8; c++) {
        const unsigned char* ap = &sa[(cbase + c)*196];
        const unsigned char* wp = &sw[(cbase + c)*25];
        #pragma unroll
        for (int ky = 0; ky < 5; ky++) {
            int iy = y + ky - 2;
            #pragma unroll
            for (int kx = 0; kx < 5; kx++) {
                int ix = x + kx - 2;
                if ((unsigned)iy < 14u && (unsigned)ix < 14u)
                    s += (ap[iy*14 + ix] * wp[ky*5 + kx]) >> 8;
            }
        }
    }
    psum[kc][pos] = s;
    __syncthreads();

    if (t < 49) {
        int py = t / 7, px = t % 7;
        int best = INT_MIN_V;
        #pragma unroll
        for (int dy = 0; dy < 2; dy++)
        #pragma unroll
        for (int dx = 0; dx < 2; dx++) {
            int p = (2*py + dy)*14 + (2*px + dx);
            best = max(best, psum[0][p] + psum[1][p]);
        }
        float v = fmaxf((float)best + b2[o], 0.0f);
        g_act2[(b*32 + o)*49 + t] = v;
        atomicMax(&smax, __float_as_int(v));
    }
    __syncthreads();
    if (t == 0) atomicMax(&g_maxbits[IX_A2], smax);
}

// conv3: in (b,32,7,7), w (64,800), pad 2, relu, pool2(pad=1) -> act3 (b,64,4,4)
// block = (b,o), 392 threads: kc = t/49 (8 chunks of 100), pos = t%49
__global__ void k_conv3(const float* __restrict__ b3) {
    int blk = blockIdx.x; int b = blk >> 6, o = blk & 63;
    __shared__ unsigned char sa[1568];         // 32*7*7
    __shared__ unsigned char sw[800];
    __shared__ int psum[8][49];
    __shared__ int tot[49];
    __shared__ int smax;
    int t = threadIdx.x;                       // 392
    for (int i = t; i < 1568; i += 392) sa[i] = g_qact2[b*1568 + i];
    for (int i = t; i < 800;  i += 392) sw[i] = g_qw3[o*800 + i];
    if (t == 0) smax = 0;
    __syncthreads();

    int kc = t / 49, pos = t % 49;
    int y = pos / 7, x = pos % 7;
    int s = 0;
    int cbase = kc * 4;                        // 100 = 4 channels * 25
    for (int c = 0; c < 4; c++) {
        const unsigned char* ap = &sa[(cbase + c)*49];
        const unsigned char* wp = &sw[(cbase + c)*25];
        #pragma unroll
        for (int ky = 0; ky < 5; ky++) {
            int iy = y + ky - 2;
            #pragma unroll
            for (int kx = 0; kx < 5; kx++) {
                int ix = x + kx - 2;
                if ((unsigned)iy < 7u && (unsigned)ix < 7u)
                    s += (ap[iy*7 + ix] * wp[ky*5 + kx]) >> 8;
            }
        }
    }
    psum[kc][pos] = s;
    __syncthreads();

    if (t < 49) {
        int v = 0;
        #pragma unroll
        for (int k = 0; k < 8; k++) v += psum[k][t];
        tot[t] = v;
    }
    __syncthreads();

    if (t < 16) {
        int py = t >> 2, px = t & 3;
        int best = INT_MIN_V;
        // pad=1 pooling: window j covers real rows {2j-1, 2j}
        #pragma unroll
        for (int dy = 0; dy < 2; dy++) {
            int ry = 2*py - 1 + dy;
            if ((unsigned)ry >= 7u) continue;
            #pragma unroll
            for (int dx = 0; dx < 2; dx++) {
                int rx = 2*px - 1 + dx;
                if ((unsigned)rx >= 7u) continue;
                best = max(best, tot[ry*7 + rx]);
            }
        }
        float v = fmaxf((float)best + b3[o], 0.0f);
        g_act3[b*1024 + o*16 + t] = v;
        atomicMax(&smax, __float_as_int(v));
    }
    __syncthreads();
    if (t == 0) atomicMax(&g_maxbits[IX_A3], smax);
}

// fc1: (b,1024) x (256,1024) -> relu -> fc1 (b,256).  block = b, 256 threads (one per out)
__global__ void k_fc1(const float* __restrict__ fb1) {
    int b = blockIdx.x;
    __shared__ unsigned char sa[1024];
    __shared__ int smax;
    int t = threadIdx.x;                       // 256
    const uint4* src4 = (const uint4*)&g_qact3[b*1024];
    if (t < 64) ((uint4*)sa)[t] = src4[t];
    if (t == 0) smax = 0;
    __syncthreads();

    const uint4* w4 = (const uint4*)&g_qfw1[t*1024];
    int s = 0;
    #pragma unroll 4
    for (int i = 0; i < 64; i++) {
        uint4 v = __ldg(&w4[i]);
        const unsigned char* ap = &sa[i*16];
        unsigned int w;
        w = v.x;
        s += (ap[0]  * (w & 255)) >> 8; s += (ap[1]  * ((w >> 8)  & 255)) >> 8;
        s += (ap[2]  * ((w >> 16) & 255)) >> 8; s += (ap[3]  * (w >> 24)) >> 8;
        w = v.y;
        s += (ap[4]  * (w & 255)) >> 8; s += (ap[5]  * ((w >> 8)  & 255)) >> 8;
        s += (ap[6]  * ((w >> 16) & 255)) >> 8; s += (ap[7]  * (w >> 24)) >> 8;
        w = v.z;
        s += (ap[8]  * (w & 255)) >> 8; s += (ap[9]  * ((w >> 8)  & 255)) >> 8;
        s += (ap[10] * ((w >> 16) & 255)) >> 8; s += (ap[11] * (w >> 24)) >> 8;
        w = v.w;
        s += (ap[12] * (w & 255)) >> 8; s += (ap[13] * ((w >> 8)  & 255)) >> 8;
        s += (ap[14] * ((w >> 16) & 255)) >> 8; s += (ap[15] * (w >> 24)) >> 8;
    }
    float v = fmaxf((float)s + fb1[t], 0.0f);
    g_fc1[b*256 + t] = v;
    atomicMax(&smax, __float_as_int(v));
    __syncthreads();
    if (t == 0) atomicMax(&g_maxbits[IX_F1], smax);
}

// fc2 + log_softmax.  block = b, 32 threads.
__global__ void k_fc2(const float* __restrict__ fb2, float* __restrict__ out) {
    int b = blockIdx.x;
    __shared__ unsigned char sa[256];
    __shared__ float vals[10];
    __shared__ float red[2];
    int t = threadIdx.x;                       // 32
    for (int i = t; i < 256; i += 32) sa[i] = g_qfc1[b*256 + i];
    __syncthreads();

    if (t < 10) {
        const unsigned char* wp = &g_qfw2[t*256];
        int s = 0;
        for (int k = 0; k < 256; k++) s += (sa[k] * wp[k]) >> 8;
        vals[t] = (float)s + fb2[t];
    }
    __syncthreads();
    if (t == 0) {
        float m = vals[0];
        #pragma unroll
        for (int i = 1; i < 10; i++) m = fmaxf(m, vals[i]);
        float se = 0.0f;
        #pragma unroll
        for (int i = 0; i < 10; i++) se += expf(vals[i] - m);
        red[0] = m; red[1] = logf(se);
    }
    __syncthreads();
    if (t < 10) out[b*10 + t] = vals[t] - red[0] - red[1];
}

// ---------------- launch ----------------
extern "C" void kernel_launch(void* const* d_in, const int* in_sizes, int n_in,
                              void* d_out, int out_size) {
    const float* x   = (const float*)d_in[0];
    // d_in[1] = lut — unused: lut[a][b] == (a*b)>>8 exactly
    const float* w1  = (const float*)d_in[2];
    const float* b1  = (const float*)d_in[3];
    const float* w2  = (const float*)d_in[4];
    const float* b2  = (const float*)d_in[5];
    const float* w3  = (const float*)d_in[6];
    const float* b3  = (const float*)d_in[7];
    const float* fw1 = (const float*)d_in[8];
    const float* fb1 = (const float*)d_in[9];
    const float* fw2 = (const float*)d_in[10];
    const float* fb2 = (const float*)d_in[11];
    float* out = (float*)d_out;

    k_init<<<1, 32>>>();
    k_max_inputs<<<dim3(32, 6), 256>>>(x, w1, w2, w3, fw1, fw2);
    k_quant_inputs<<<dim3(64, 6), 256>>>(x, w1, w2, w3, fw1, fw2);

    k_conv1<<<NB*16, 196>>>(b1);
    k_quant_act<<<64, 256>>>(0);

    k_conv2<<<NB*32, 392>>>(b2);
    k_quant_act<<<64, 256>>>(1);

    k_conv3<<<NB*64, 392>>>(b3);
    k_quant_act<<<64, 256>>>(2);

    k_fc1<<<NB, 256>>>(fb1);
    k_quant_act<<<32, 256>>>(3);

    k_fc2<<<NB, 32>>>(fb2, out);
}

// round 2
// speedup vs baseline: 1.5211x; 1.5211x over previous
#include <cuda_runtime.h>
#include <math.h>

#define NB 32
#define INT_MIN_V ((int)0x80000000)

// pmax slots (inputs): 0=x 1=w1 2=w2 3=w3 4=fw1 5=fw2
// maxbits slots (activations, atomic): 6=A1 7=A2 8=A3 9=F1
__device__ float g_pmax[6*32];
__device__ int   g_maxbits[10];

__device__ __align__(16) unsigned char g_qfw1[256*1024];

__device__ float g_act1[NB*16*196];   // (b,16,14,14) pooled
__device__ float g_act2[NB*32*49];    // (b,32,7,7)
__device__ float g_act3[NB*64*16];    // (b,64,4,4)
__device__ float g_fc1 [NB*256];

// ---------------- helpers ----------------
__device__ __forceinline__ float scale_from_pmax(int idx) {
    float m = 0.0f;
    #pragma unroll
    for (int i = 0; i < 32; i++) m = fmaxf(m, g_pmax[idx*32 + i]);
    return __fdiv_rn(255.0f, fmaxf(m, 1e-6f));
}
__device__ __forceinline__ float scale_from_bits(int idx) {
    float m = __int_as_float(g_maxbits[idx]);
    return __fdiv_rn(255.0f, fmaxf(m, 1e-6f));
}
__device__ __forceinline__ unsigned char quant1(float v, float s) {
    float r = rintf(__fmul_rn(v, s));            // half-even, matches jnp.round
    r = fminf(fmaxf(r, 0.0f), 255.0f);
    return (unsigned char)(int)r;
}
// packed MAC: win holds >=6 bytes starting at col base; produces sum of two
// exact (a*w)>>8 terms in 16-bit halves of acc
__device__ __forceinline__ unsigned packed_mac(unsigned long long win, int kx, unsigned wv) {
    unsigned sp = __byte_perm((unsigned)(win >> (8*kx)), 0u, 0x4140);  // [a0,0,a1,0]
    unsigned pr = sp * wv;                                             // two 16-bit products
    return __byte_perm(pr, 0u, 0x4341);                                // [hi0,0,hi1,0]
}

// ---------------- k_max: partial maxima + reset activation slots ----------------
__global__ void k_max(const float* __restrict__ x,  const float* __restrict__ w1,
                      const float* __restrict__ w2, const float* __restrict__ w3,
                      const float* __restrict__ fw1,const float* __restrict__ fw2) {
    int idx = blockIdx.y, bx = blockIdx.x;
    const float* src; int n;
    switch (idx) {
        case 0: src = x;   n = NB*784;   break;
        case 1: src = w1;  n = 16*25;    break;
        case 2: src = w2;  n = 32*400;   break;
        case 3: src = w3;  n = 64*800;   break;
        case 4: src = fw1; n = 256*1024; break;
        default:src = fw2; n = 10*256;   break;
    }
    float m = 0.0f;
    for (int i = bx*blockDim.x + threadIdx.x; i < n; i += gridDim.x*blockDim.x)
        m = fmaxf(m, fabsf(src[i]));
    __shared__ int sm;
    if (threadIdx.x == 0) sm = 0;
    __syncthreads();
    atomicMax(&sm, __float_as_int(m));
    __syncthreads();
    if (threadIdx.x == 0) {
        g_pmax[idx*32 + bx] = __int_as_float(sm);
        if (idx == 0 && bx == 0) {
            g_maxbits[6] = 0; g_maxbits[7] = 0; g_maxbits[8] = 0; g_maxbits[9] = 0;
        }
    }
}

// ---------------- conv1: (b,1,28,28) -> relu+pool -> act1 (b,16,14,14) ----------------
// grid 256 = (b, og of 2 outputs), block 392 = (o_local 2) x (pooled pos 196)
__global__ void k_conv1(const float* __restrict__ x, const float* __restrict__ w1,
                        const float* __restrict__ b1, const float* __restrict__ fw1) {
    int blk = blockIdx.x; int b = blk >> 3, o0 = (blk & 7)*2;
    __shared__ unsigned char sa[32*32];         // padded input, zero border
    __shared__ unsigned char sw[2*32];
    __shared__ float sc[3];                     // sx, sw1, sfw1
    __shared__ int smax;
    int t = threadIdx.x;                        // 392

    if (t == 0) {
        sc[0] = scale_from_pmax(0);
        sc[1] = scale_from_pmax(1);
        sc[2] = scale_from_pmax(4);
        smax = 0;
    }
    for (int i = t; i < 256; i += 392) ((unsigned*)sa)[i] = 0u;
    __syncthreads();

    float sx = sc[0], sw1s = sc[1], sfw1 = sc[2];
    for (int i = t; i < 784; i += 392) {
        int r = i / 28, c = i % 28;
        sa[(r+2)*32 + (c+2)] = quant1(x[b*784 + i], sx);
    }
    if (t < 50) {
        int ol = t / 25, k = t % 25;
        sw[ol*32 + k] = quant1(w1[(o0+ol)*25 + k], sw1s);
    }
    // quantize this block's 1/256 slice of fw1 (for fc1 later)
    {
        int base = blk * 1024;
        for (int i = t; i < 1024; i += 392)
            g_qfw1[base + i] = quant1(fw1[base + i], sfw1);
    }
    __syncthreads();

    int ol = (t >= 196) ? 1 : 0;
    int pos = t - ol*196;
    int py = pos / 14, px = pos % 14;
    int cb = 2*px, off = cb & 3, alo = cb - off;

    unsigned long long win[6];
    #pragma unroll
    for (int rr = 0; rr < 6; rr++) {
        int addr = (2*py + rr)*32 + alo;
        unsigned lo = *(const unsigned*)(sa + addr);
        unsigned hi = *(const unsigned*)(sa + addr + 4);
        win[rr] = ((((unsigned long long)hi) << 32) | lo) >> (8*off);
    }
    unsigned acc0 = 0, acc1 = 0;
    #pragma unroll
    for (int ky = 0; ky < 5; ky++) {
        #pragma unroll
        for (int kx = 0; kx < 5; kx++) {
            unsigned wv = sw[ol*32 + ky*5 + kx];
            acc0 += packed_mac(win[ky],   kx, wv);
            acc1 += packed_mac(win[ky+1], kx, wv);
        }
    }
    int s00 = acc0 & 0xFFFF, s01 = acc0 >> 16;
    int s10 = acc1 & 0xFFFF, s11 = acc1 >> 16;
    int best = max(max(s00, s01), max(s10, s11));
    int o = o0 + ol;
    float v = fmaxf((float)best + b1[o], 0.0f);
    g_act1[(b*16 + o)*196 + pos] = v;
    atomicMax(&smax, __float_as_int(v));
    __syncthreads();
    if (t == 0) atomicMax(&g_maxbits[6], smax);
}

// ---------------- conv2: (b,16,14,14) -> relu+pool -> act2 (b,32,7,7) ----------------
// grid 1024 = (b,o), block 392 = (kc 8 chunks of 2ch) x (pooled pos 49)
__global__ void k_conv2(const float* __restrict__ w2, const float* __restrict__ b2) {
    int blk = blockIdx.x; int b = blk >> 5, o = blk & 31;
    __shared__ unsigned char sa[16*18*20];      // padded: ch stride 360, row stride 20
    __shared__ unsigned char sw[400];
    __shared__ int psum[8*49*4];
    __shared__ float sc[2];
    __shared__ int smax;
    int t = threadIdx.x;                        // 392

    if (t == 0) { sc[0] = scale_from_bits(6); sc[1] = scale_from_pmax(2); smax = 0; }
    for (int i = t; i < 1440; i += 392) ((unsigned*)sa)[i] = 0u;   // 5760 bytes
    __syncthreads();

    float sa1 = sc[0], sw2s = sc[1];
    for (int i = t; i < 3136; i += 392) {
        int ch = i / 196, rem = i - ch*196;
        int r = rem / 14, c = rem % 14;
        sa[ch*360 + (r+2)*20 + (c+2)] = quant1(g_act1[b*3136 + i], sa1);
    }
    for (int i = t; i < 400; i += 392)
        sw[i] = quant1(w2[o*400 + i], sw2s);
    __syncthreads();

    int kc = t / 49, pos = t - kc*49;
    int py = pos / 7, px = pos % 7;
    int cb = 2*px, off = cb & 3, alo = cb - off;

    unsigned acc0 = 0, acc1 = 0;
    #pragma unroll
    for (int cc = 0; cc < 2; cc++) {
        int ch = kc*2 + cc;
        const unsigned char* base = sa + ch*360;
        unsigned long long win[6];
        #pragma unroll
        for (int rr = 0; rr < 6; rr++) {
            int addr = (2*py + rr)*20 + alo;
            unsigned lo = *(const unsigned*)(base + addr);
            unsigned hi = *(const unsigned*)(base + addr + 4);
            win[rr] = ((((unsigned long long)hi) << 32) | lo) >> (8*off);
        }
        const unsigned char* wp = sw + ch*25;
        #pragma unroll
        for (int ky = 0; ky < 5; ky++) {
            #pragma unroll
            for (int kx = 0; kx < 5; kx++) {
                unsigned wv = wp[ky*5 + kx];
                acc0 += packed_mac(win[ky],   kx, wv);
                acc1 += packed_mac(win[ky+1], kx, wv);
            }
        }
    }
    int base4 = (kc*49 + pos)*4;
    psum[base4 + 0] = acc0 & 0xFFFF; psum[base4 + 1] = acc0 >> 16;
    psum[base4 + 2] = acc1 & 0xFFFF; psum[base4 + 3] = acc1 >> 16;
    __syncthreads();

    if (t < 49) {
        int s0 = 0, s1 = 0, s2 = 0, s3 = 0;
        #pragma unroll
        for (int k = 0; k < 8; k++) {
            int bi = (k*49 + t)*4;
            s0 += psum[bi]; s1 += psum[bi+1]; s2 += psum[bi+2]; s3 += psum[bi+3];
        }
        int best = max(max(s0, s1), max(s2, s3));
        float v = fmaxf((float)best + b2[o], 0.0f);
        g_act2[(b*32 + o)*49 + t] = v;
        atomicMax(&smax, __float_as_int(v));
    }
    __syncthreads();
    if (t == 0) atomicMax(&g_maxbits[7], smax);
}

// ---------------- conv3: (b,32,7,7) -> relu+pool(pad=1) -> act3 (b,64,4,4) --------
// grid 2048 = (b,o), block 448 = (kc 16 chunks of 2ch) x (y 7) x (xpair 4)
__global__ void k_conv3(const float* __restrict__ w3, const float* __restrict__ b3) {
    int blk = blockIdx.x; int b = blk >> 6, o = blk & 63;
    __shared__ unsigned char sa[32*11*12];      // padded: ch stride 132, row stride 12
    __shared__ unsigned char sw[800];
    __shared__ int convs[16*56];                // per-kc partial conv values (y*8+x)
    __shared__ int stot[56];
    __shared__ float sc[2];
    __shared__ int smax;
    int t = threadIdx.x;                        // 448

    if (t == 0) { sc[0] = scale_from_bits(7); sc[1] = scale_from_pmax(3); smax = 0; }
    for (int i = t; i < 1056; i += 448) ((unsigned*)sa)[i] = 0u;   // 4224 bytes
    __syncthreads();

    float sa2 = sc[0], sw3s = sc[1];
    for (int i = t; i < 1568; i += 448) {
        int ch = i / 49, rem = i - ch*49;
        int r = rem / 7, c = rem % 7;
        sa[ch*132 + (r+2)*12 + (c+2)] = quant1(g_act2[b*1568 + i], sa2);
    }
    for (int i = t; i < 800; i += 448)
        sw[i] = quant1(w3[o*800 + i], sw3s);
    __syncthreads();

    int kc = t / 28, idx = t - kc*28;
    int y = idx / 4, x0 = (idx & 3)*2;
    int off = x0 & 3, alo = x0 - off;

    unsigned acc = 0;
    #pragma unroll
    for (int cc = 0; cc < 2; cc++) {
        int ch = kc*2 + cc;
        const unsigned char* base = sa + ch*132;
        unsigned long long win[5];
        #pragma unroll
        for (int rr = 0; rr < 5; rr++) {
            int addr = (y + rr)*12 + alo;
            unsigned lo = *(const unsigned*)(base + addr);
            unsigned hi = *(const unsigned*)(base + addr + 4);
            win[rr] = ((((unsigned long long)hi) << 32) | lo) >> (8*off);
        }
        const unsigned char* wp = sw + ch*25;
        #pragma unroll
        for (int ky = 0; ky < 5; ky++) {
            #pragma unroll
            for (int kx = 0; kx < 5; kx++) {
                acc += packed_mac(win[ky], kx, (unsigned)wp[ky*5 + kx]);
            }
        }
    }
    convs[kc*56 + y*8 + x0]     = acc & 0xFFFF;
    convs[kc*56 + y*8 + x0 + 1] = acc >> 16;     // x0+1==7 is garbage, never pooled
    __syncthreads();

    if (t < 56) {
        int s = 0;
        #pragma unroll
        for (int k = 0; k < 16; k++) s += convs[k*56 + t];
        stot[t] = s;
    }
    __syncthreads();

    if (t < 16) {
        int py = t >> 2, px = t & 3;
        int best = INT_MIN_V;
        #pragma unroll
        for (int dy = 0; dy < 2; dy++) {
            int ry = 2*py - 1 + dy;
            if ((unsigned)ry >= 7u) continue;
            #pragma unroll
            for (int dx = 0; dx < 2; dx++) {
                int rx = 2*px - 1 + dx;
                if ((unsigned)rx >= 7u) continue;
                best = max(best, stot[ry*8 + rx]);
            }
        }
        float v = fmaxf((float)best + b3[o], 0.0f);
        g_act3[b*1024 + o*16 + t] = v;
        atomicMax(&smax, __float_as_int(v));
    }
    __syncthreads();
    if (t == 0) atomicMax(&g_maxbits[8], smax);
}

// ---------------- fc1: (b,1024)x(256,1024) -> relu -> g_fc1 ----------------
// grid 256 = (b, og of 32 outputs), block 256 = (o_local 32) x (kslice 8)
__global__ void k_fc1(const float* __restrict__ fb1) {
    int blk = blockIdx.x; int b = blk >> 3, og = blk & 7;
    __shared__ unsigned char qa[1024];
    __shared__ int red[256];
    __shared__ float sc1;
    __shared__ int smax;
    int t = threadIdx.x;                        // 256

    if (t == 0) { sc1 = scale_from_bits(8); smax = 0; }
    __syncthreads();
    float sa3 = sc1;
    #pragma unroll
    for (int i = 0; i < 4; i++) {
        int k = t + i*256;
        qa[k] = quant1(g_act3[b*1024 + k], sa3);
    }
    __syncthreads();

    int ol = t >> 3, ks = t & 7;
    int o = og*32 + ol;
    const unsigned* wp = (const unsigned*)(g_qfw1 + o*1024 + ks*128);
    const unsigned* ap = (const unsigned*)(qa + ks*128);
    int s = 0;
    #pragma unroll 8
    for (int i = 0; i < 32; i++) {
        unsigned w4 = wp[i], a4 = ap[i];
        s += ((a4 & 255u)        * (w4 & 255u))        >> 8;
        s += (((a4 >> 8) & 255u) * ((w4 >> 8) & 255u)) >> 8;
        s += (((a4 >>16) & 255u) * ((w4 >>16) & 255u)) >> 8;
        s += ((a4 >> 24)         * (w4 >> 24))         >> 8;
    }
    red[t] = s;
    __syncthreads();
    if (ks == 0) {
        int tot = 0;
        #pragma unroll
        for (int i = 0; i < 8; i++) tot += red[t + i];
        float v = fmaxf((float)tot + fb1[o], 0.0f);
        g_fc1[b*256 + o] = v;
        atomicMax(&smax, __float_as_int(v));
    }
    __syncthreads();
    if (t == 0) atomicMax(&g_maxbits[9], smax);
}

// ---------------- fc2 + log_softmax. grid 32 (b), block 128 ----------------
__global__ void k_fc2(const float* __restrict__ fw2, const float* __restrict__ fb2,
                      float* __restrict__ out) {
    int b = blockIdx.x;
    __shared__ unsigned char qa[256];
    __shared__ unsigned char qw[2560];
    __shared__ int red[80];
    __shared__ float vals[10];
    __shared__ float mred[2];
    __shared__ float sc[2];
    int t = threadIdx.x;                        // 128

    if (t == 0) { sc[0] = scale_from_bits(9); sc[1] = scale_from_pmax(5); }
    __syncthreads();
    float sf1 = sc[0], sfw2 = sc[1];
    for (int i = t; i < 256; i += 128) qa[i] = quant1(g_fc1[b*256 + i], sf1);
    for (int i = t; i < 2560; i += 128) qw[i] = quant1(fw2[i], sfw2);
    __syncthreads();

    if (t < 80) {
        int o = t >> 3, ks = t & 7;
        const unsigned char* wp = qw + o*256 + ks*32;
        const unsigned char* ap = qa + ks*32;
        int s = 0;
        #pragma unroll
        for (int k = 0; k < 32; k++) s += (ap[k] * wp[k]) >> 8;
        red[t] = s;
    }
    __syncthreads();
    if (t < 10) {
        int s = 0;
        #pragma unroll
        for (int i = 0; i < 8; i++) s += red[t*8 + i];
        vals[t] = (float)s + fb2[t];
    }
    __syncthreads();
    if (t == 0) {
        float m = vals[0];
        #pragma unroll
        for (int i = 1; i < 10; i++) m = fmaxf(m, vals[i]);
        float se = 0.0f;
        #pragma unroll
        for (int i = 0; i < 10; i++) se += expf(vals[i] - m);
        mred[0] = m; mred[1] = logf(se);
    }
    __syncthreads();
    if (t < 10) out[b*10 + t] = vals[t] - mred[0] - mred[1];
}

// ---------------- launch ----------------
extern "C" void kernel_launch(void* const* d_in, const int* in_sizes, int n_in,
                              void* d_out, int out_size) {
    const float* x   = (const float*)d_in[0];
    // d_in[1] = lut — unused: lut[a][b] == (a*b)>>8 exactly
    const float* w1  = (const float*)d_in[2];
    const float* b1  = (const float*)d_in[3];
    const float* w2  = (const float*)d_in[4];
    const float* b2  = (const float*)d_in[5];
    const float* w3  = (const float*)d_in[6];
    const float* b3  = (const float*)d_in[7];
    const float* fw1 = (const float*)d_in[8];
    const float* fb1 = (const float*)d_in[9];
    const float* fw2 = (const float*)d_in[10];
    const float* fb2 = (const float*)d_in[11];
    float* out = (float*)d_out;

    k_max  <<<dim3(32, 6), 256>>>(x, w1, w2, w3, fw1, fw2);
    k_conv1<<<256, 392>>>(x, w1, b1, fw1);
    k_conv2<<<1024, 392>>>(w2, b2);
    k_conv3<<<2048, 448>>>(w3, b3);
    k_fc1  <<<256, 256>>>(fb1);
    k_fc2  <<<32, 128>>>(fw2, fb2, out);
}

// round 3
// speedup vs baseline: 1.8656x; 1.2265x over previous
#include <cuda_runtime.h>
#include <math.h>

#define NB 32
#define INT_MIN_V ((int)0x80000000)

// pmax slots (inputs): 0=x 1=w1 2=w2 3=w3 4=fw1 5=fw2
// maxbits slots (activations, atomic): 6=A1 7=A2 8=A3 9=F1
__device__ float g_pmax[6*32];
__device__ int   g_maxbits[10];

__device__ __align__(16) unsigned char g_qx  [NB*784];
__device__ __align__(16) unsigned char g_qw1 [16*25];
__device__ __align__(16) unsigned char g_qw2 [32*400];
__device__ __align__(16) unsigned char g_qw3 [64*800];
__device__ __align__(16) unsigned      g_qfw1s[128*1024];  // spread: [w(2op) | w(2op+1)<<16]
__device__ __align__(16) unsigned char g_qfw2[10*256];

__device__ float g_act1[NB*16*196];   // (b,16,14,14)
__device__ float g_act2[NB*32*49];    // (b,32,7,7)
__device__ float g_act3[NB*64*16];    // (b,64,4,4)
__device__ float g_fc1 [NB*256];

// ---------------- helpers ----------------
__device__ __forceinline__ float scale_from_pmax(int idx) {
    float m = 0.0f;
    #pragma unroll
    for (int i = 0; i < 32; i++) m = fmaxf(m, g_pmax[idx*32 + i]);
    return __fdiv_rn(255.0f, fmaxf(m, 1e-6f));
}
__device__ __forceinline__ float scale_from_bits(int idx) {
    float m = __int_as_float(g_maxbits[idx]);
    return __fdiv_rn(255.0f, fmaxf(m, 1e-6f));
}
__device__ __forceinline__ unsigned char quant1(float v, float s) {
    float r = rintf(__fmul_rn(v, s));            // half-even == jnp.round
    r = fminf(fmaxf(r, 0.0f), 255.0f);
    return (unsigned char)(int)r;
}
// two exact (a*w)>>8 terms in 16-bit halves
__device__ __forceinline__ unsigned packed_mac(unsigned long long win, int kx, unsigned wv) {
    unsigned sp = __byte_perm((unsigned)(win >> (8*kx)), 0u, 0x4140);  // [a0,0,a1,0]
    unsigned pr = sp * wv;
    return __byte_perm(pr, 0u, 0x4341);                                // [hi0,0,hi1,0]
}

// ---------------- k_max ----------------
__global__ void k_max(const float* __restrict__ x,  const float* __restrict__ w1,
                      const float* __restrict__ w2, const float* __restrict__ w3,
                      const float* __restrict__ fw1,const float* __restrict__ fw2) {
    int idx = blockIdx.y, bx = blockIdx.x;
    const float* src; int n;
    switch (idx) {
        case 0: src = x;   n = NB*784;   break;
        case 1: src = w1;  n = 16*25;    break;
        case 2: src = w2;  n = 32*400;   break;
        case 3: src = w3;  n = 64*800;   break;
        case 4: src = fw1; n = 256*1024; break;
        default:src = fw2; n = 10*256;   break;
    }
    float m = 0.0f;
    for (int i = bx*blockDim.x + threadIdx.x; i < n; i += gridDim.x*blockDim.x)
        m = fmaxf(m, fabsf(src[i]));
    __shared__ int sm;
    if (threadIdx.x == 0) sm = 0;
    __syncthreads();
    atomicMax(&sm, __float_as_int(m));
    __syncthreads();
    if (threadIdx.x == 0) {
        g_pmax[idx*32 + bx] = __int_as_float(sm);
        if (idx == 0 && bx == 0) {
            g_maxbits[6] = 0; g_maxbits[7] = 0; g_maxbits[8] = 0; g_maxbits[9] = 0;
        }
    }
}

// ---------------- k_qw: quantize inputs + all weights (fw1 pre-spread) --------
__global__ void k_qw(const float* __restrict__ x,  const float* __restrict__ w1,
                     const float* __restrict__ w2, const float* __restrict__ w3,
                     const float* __restrict__ fw1,const float* __restrict__ fw2) {
    int idx = blockIdx.y;
    __shared__ float ssc;
    if (threadIdx.x == 0) {
        int slot = (idx == 0) ? 0 : (idx <= 3 ? idx : (idx == 4 ? 4 : 5));
        ssc = scale_from_pmax(slot);
    }
    __syncthreads();
    float s = ssc;
    int tid = blockIdx.x*blockDim.x + threadIdx.x, stride = gridDim.x*blockDim.x;

    if (idx == 0) {
        for (int i = tid; i < NB*784; i += stride) g_qx[i] = quant1(x[i], s);
    } else if (idx == 1) {
        for (int i = tid; i < 16*25; i += stride) g_qw1[i] = quant1(w1[i], s);
    } else if (idx == 2) {
        for (int i = tid; i < 32*400; i += stride) g_qw2[i] = quant1(w2[i], s);
    } else if (idx == 3) {
        for (int i = tid; i < 64*800; i += stride) g_qw3[i] = quant1(w3[i], s);
    } else if (idx == 4) {
        // spread: uint i -> op = i>>10, k = i&1023
        for (int i = tid; i < 128*1024; i += stride) {
            int op = i >> 10, k = i & 1023;
            unsigned lo = quant1(fw1[(2*op)*1024 + k], s);
            unsigned hi = quant1(fw1[(2*op+1)*1024 + k], s);
            g_qfw1s[i] = lo | (hi << 16);
        }
    } else {
        for (int i = tid; i < 10*256; i += stride) g_qfw2[i] = quant1(fw2[i], s);
    }
}

// ---------------- conv1: qx (b,28,28) -> relu+pool -> act1 ----------------
// grid 256 = (b, og8 of 2 o), block 392
__global__ void k_conv1(const float* __restrict__ b1) {
    int blk = blockIdx.x; int b = blk >> 3, o0 = (blk & 7)*2;
    __shared__ unsigned char sa[32*32];
    __shared__ unsigned char sw[2*32];
    __shared__ int smax;
    int t = threadIdx.x;                        // 392

    if (t == 0) smax = 0;
    for (int i = t; i < 256; i += 392) ((unsigned*)sa)[i] = 0u;
    __syncthreads();
    for (int i = t; i < 784; i += 392) {
        int r = i / 28, c = i % 28;
        sa[(r+2)*32 + (c+2)] = g_qx[b*784 + i];
    }
    if (t < 50) {
        int ol = t / 25, k = t % 25;
        sw[ol*32 + k] = g_qw1[(o0+ol)*25 + k];
    }
    __syncthreads();

    int ol = (t >= 196) ? 1 : 0;
    int pos = t - ol*196;
    int py = pos / 14, px = pos % 14;
    int cb = 2*px, off = cb & 3, alo = cb - off;

    unsigned long long win[6];
    #pragma unroll
    for (int rr = 0; rr < 6; rr++) {
        int addr = (2*py + rr)*32 + alo;
        unsigned lo = *(const unsigned*)(sa + addr);
        unsigned hi = *(const unsigned*)(sa + addr + 4);
        win[rr] = ((((unsigned long long)hi) << 32) | lo) >> (8*off);
    }
    unsigned acc0 = 0, acc1 = 0;
    #pragma unroll
    for (int ky = 0; ky < 5; ky++) {
        #pragma unroll
        for (int kx = 0; kx < 5; kx++) {
            unsigned wv = sw[ol*32 + ky*5 + kx];
            acc0 += packed_mac(win[ky],   kx, wv);
            acc1 += packed_mac(win[ky+1], kx, wv);
        }
    }
    int best = max(max((int)(acc0 & 0xFFFF), (int)(acc0 >> 16)),
                   max((int)(acc1 & 0xFFFF), (int)(acc1 >> 16)));
    int o = o0 + ol;
    float v = fmaxf((float)best + b1[o], 0.0f);
    g_act1[(b*16 + o)*196 + pos] = v;
    atomicMax(&smax, __float_as_int(v));
    __syncthreads();
    if (t == 0) atomicMax(&g_maxbits[6], smax);
}

// ---------------- conv2: act1 (b,16,14,14) -> relu+pool -> act2 ----------------
// grid 256 = (b, og8 of 4 o), block 784 = o_l(4) x kc(4, 4ch each) x pos(49)
__global__ void k_conv2(const float* __restrict__ b2) {
    int blk = blockIdx.x; int b = blk >> 3, o0 = (blk & 7)*4;
    __shared__ unsigned char sa[16*18*20];      // ch stride 360, row stride 20
    __shared__ unsigned char sw[1600];
    __shared__ int psum[16*49*4];               // (o_l*4+kc)*196 + pos*4 + j
    __shared__ float sc1;
    __shared__ int smax;
    int t = threadIdx.x;                        // 784

    if (t == 0) { sc1 = scale_from_bits(6); smax = 0; }
    for (int i = t; i < 1440; i += 784) ((unsigned*)sa)[i] = 0u;
    __syncthreads();

    float sa1 = sc1;
    for (int i = t; i < 3136; i += 784) {
        int ch = i / 196, rem = i - ch*196;
        int r = rem / 14, c = rem % 14;
        sa[ch*360 + (r+2)*20 + (c+2)] = quant1(g_act1[b*3136 + i], sa1);
    }
    if (t < 100) ((uint4*)sw)[t] = ((const uint4*)(g_qw2 + o0*400))[t];
    __syncthreads();

    int o_l = t / 196, rem = t - o_l*196;
    int kc = rem / 49, pos = rem - kc*49;
    int py = pos / 7, px = pos % 7;
    int cb = 2*px, off = cb & 3, alo = cb - off;

    unsigned acc0 = 0, acc1 = 0;
    #pragma unroll
    for (int cc = 0; cc < 4; cc++) {
        int ch = kc*4 + cc;
        const unsigned char* base = sa + ch*360;
        unsigned long long win[6];
        #pragma unroll
        for (int rr = 0; rr < 6; rr++) {
            int addr = (2*py + rr)*20 + alo;
            unsigned lo = *(const unsigned*)(base + addr);
            unsigned hi = *(const unsigned*)(base + addr + 4);
            win[rr] = ((((unsigned long long)hi) << 32) | lo) >> (8*off);
        }
        const unsigned char* wp = sw + o_l*400 + ch*25;
        #pragma unroll
        for (int ky = 0; ky < 5; ky++) {
            #pragma unroll
            for (int kx = 0; kx < 5; kx++) {
                unsigned wv = wp[ky*5 + kx];
                acc0 += packed_mac(win[ky],   kx, wv);
                acc1 += packed_mac(win[ky+1], kx, wv);
            }
        }
    }
    int base4 = ((o_l*4 + kc)*49 + pos)*4;
    psum[base4 + 0] = acc0 & 0xFFFF; psum[base4 + 1] = acc0 >> 16;
    psum[base4 + 2] = acc1 & 0xFFFF; psum[base4 + 3] = acc1 >> 16;
    __syncthreads();

    if (t < 196) {
        int o_r = t / 49, p = t - o_r*49;
        int s0 = 0, s1 = 0, s2 = 0, s3 = 0;
        #pragma unroll
        for (int k = 0; k < 4; k++) {
            int bi = ((o_r*4 + k)*49 + p)*4;
            s0 += psum[bi]; s1 += psum[bi+1]; s2 += psum[bi+2]; s3 += psum[bi+3];
        }
        int best = max(max(s0, s1), max(s2, s3));
        int o = o0 + o_r;
        float v = fmaxf((float)best + b2[o], 0.0f);
        g_act2[(b*32 + o)*49 + p] = v;
        atomicMax(&smax, __float_as_int(v));
    }
    __syncthreads();
    if (t == 0) atomicMax(&g_maxbits[7], smax);
}

// ---------------- conv3: act2 (b,32,7,7) -> relu+pool(pad=1) -> act3 --------
// grid 512 = (b, og16 of 4 o), block 448 = o_l(4) x kc(4, 8ch) x (y7 * xpair4)
__global__ void k_conv3(const float* __restrict__ b3) {
    int blk = blockIdx.x; int b = blk >> 4, o0 = (blk & 15)*4;
    __shared__ unsigned char sa[32*11*12];      // ch stride 132, row stride 12
    __shared__ unsigned char sw[3200];
    __shared__ int convs[16*56];                // (o_l*4+kc)*56 + y*8 + x
    __shared__ int stot[4*56];
    __shared__ float sc1;
    __shared__ int smax;
    int t = threadIdx.x;                        // 448

    if (t == 0) { sc1 = scale_from_bits(7); smax = 0; }
    for (int i = t; i < 1056; i += 448) ((unsigned*)sa)[i] = 0u;
    __syncthreads();

    float sa2 = sc1;
    for (int i = t; i < 1568; i += 448) {
        int ch = i / 49, rem = i - ch*49;
        int r = rem / 7, c = rem % 7;
        sa[ch*132 + (r+2)*12 + (c+2)] = quant1(g_act2[b*1568 + i], sa2);
    }
    for (int i = t; i < 200; i += 448) ((uint4*)sw)[i] = ((const uint4*)(g_qw3 + o0*800))[i];
    __syncthreads();

    int o_l = t / 112, rem = t - o_l*112;
    int kc = rem / 28, idx = rem - kc*28;
    int y = idx / 4, x0 = (idx & 3)*2;
    int off = x0 & 3, alo = x0 - off;

    unsigned acc = 0;
    #pragma unroll
    for (int cc = 0; cc < 8; cc++) {
        int ch = kc*8 + cc;
        const unsigned char* base = sa + ch*132;
        unsigned long long win[5];
        #pragma unroll
        for (int rr = 0; rr < 5; rr++) {
            int addr = (y + rr)*12 + alo;
            unsigned lo = *(const unsigned*)(base + addr);
            unsigned hi = *(const unsigned*)(base + addr + 4);
            win[rr] = ((((unsigned long long)hi) << 32) | lo) >> (8*off);
        }
        const unsigned char* wp = sw + o_l*800 + ch*25;
        #pragma unroll
        for (int ky = 0; ky < 5; ky++) {
            #pragma unroll
            for (int kx = 0; kx < 5; kx++) {
                acc += packed_mac(win[ky], kx, (unsigned)wp[ky*5 + kx]);
            }
        }
    }
    convs[(o_l*4 + kc)*56 + y*8 + x0]     = acc & 0xFFFF;
    convs[(o_l*4 + kc)*56 + y*8 + x0 + 1] = acc >> 16;   // x=7 garbage, never pooled
    __syncthreads();

    if (t < 224) {
        int o_r = t / 56, p = t - o_r*56;
        int s = 0;
        #pragma unroll
        for (int k = 0; k < 4; k++) s += convs[(o_r*4 + k)*56 + p];
        stot[o_r*56 + p] = s;
    }
    __syncthreads();

    if (t < 64) {
        int o_r = t >> 4, idx2 = t & 15;
        int py = idx2 >> 2, px = idx2 & 3;
        int best = INT_MIN_V;
        #pragma unroll
        for (int dy = 0; dy < 2; dy++) {
            int ry = 2*py - 1 + dy;
            if ((unsigned)ry >= 7u) continue;
            #pragma unroll
            for (int dx = 0; dx < 2; dx++) {
                int rx = 2*px - 1 + dx;
                if ((unsigned)rx >= 7u) continue;
                best = max(best, stot[o_r*56 + ry*8 + rx]);
            }
        }
        int o = o0 + o_r;
        float v = fmaxf((float)best + b3[o], 0.0f);
        g_act3[b*1024 + o*16 + idx2] = v;
        atomicMax(&smax, __float_as_int(v));
    }
    __syncthreads();
    if (t == 0) atomicMax(&g_maxbits[8], smax);
}

// ---------------- fc1: spread-weight dual-output dot ----------------
// grid 256 = (b, og8 of 32 o = 16 o-pairs), block 256 = op_l(16) x ks(16, 64 k each)
__global__ void k_fc1(const float* __restrict__ fb1) {
    int blk = blockIdx.x; int b = blk >> 3, og = blk & 7;
    __shared__ unsigned char qa[1024];
    __shared__ int red[512];                    // [parity*256 + op_l*16 + ks]
    __shared__ float sc1;
    __shared__ int smax;
    int t = threadIdx.x;                        // 256

    if (t == 0) { sc1 = scale_from_bits(8); smax = 0; }
    __syncthreads();
    float sa3 = sc1;
    #pragma unroll
    for (int i = 0; i < 4; i++) {
        int k = t + i*256;
        qa[k] = quant1(g_act3[b*1024 + k], sa3);
    }
    __syncthreads();

    int op_l = t >> 4, ks = t & 15;
    int op = og*16 + op_l;
    const uint4* wp = (const uint4*)(g_qfw1s + op*1024 + ks*64);
    const unsigned* ap = (const unsigned*)(qa + ks*64);
    unsigned acc = 0;
    #pragma unroll
    for (int i = 0; i < 16; i++) {
        uint4 w = wp[i];
        unsigned au = ap[i];
        unsigned a0 = __byte_perm(au, 0u, 0x4440);
        unsigned a1 = __byte_perm(au, 0u, 0x4441);
        unsigned a2 = __byte_perm(au, 0u, 0x4442);
        unsigned a3 = __byte_perm(au, 0u, 0x4443);
        acc += __byte_perm(w.x * a0, 0u, 0x4341);
        acc += __byte_perm(w.y * a1, 0u, 0x4341);
        acc += __byte_perm(w.z * a2, 0u, 0x4341);
        acc += __byte_perm(w.w * a3, 0u, 0x4341);
    }
    red[op_l*16 + ks]       = acc & 0xFFFF;     // even output of pair
    red[256 + op_l*16 + ks] = acc >> 16;        // odd output
    __syncthreads();

    if (t < 32) {
        int op_r = t >> 1, parity = t & 1;
        int base = parity*256 + op_r*16;
        int s = 0;
        #pragma unroll
        for (int i = 0; i < 16; i++) s += red[base + i];
        int o = og*32 + op_r*2 + parity;
        float v = fmaxf((float)s + fb1[o], 0.0f);
        g_fc1[b*256 + o] = v;
        atomicMax(&smax, __float_as_int(v));
    }
    __syncthreads();
    if (t == 0) atomicMax(&g_maxbits[9], smax);
}

// ---------------- fc2 + log_softmax. grid 32, block 128 ----------------
__global__ void k_fc2(const float* __restrict__ fb2, float* __restrict__ out) {
    int b = blockIdx.x;
    __shared__ unsigned char qa[256];
    __shared__ int red[80];
    __shared__ float vals[10];
    __shared__ float mred[2];
    __shared__ float sc1;
    int t = threadIdx.x;                        // 128

    if (t == 0) sc1 = scale_from_bits(9);
    __syncthreads();
    float sf1 = sc1;
    for (int i = t; i < 256; i += 128) qa[i] = quant1(g_fc1[b*256 + i], sf1);
    __syncthreads();

    if (t < 80) {
        int o = t >> 3, ks = t & 7;
        const unsigned char* wp = g_qfw2 + o*256 + ks*32;
        const unsigned char* ap = qa + ks*32;
        int s = 0;
        #pragma unroll
        for (int k = 0; k < 32; k++) s += (ap[k] * wp[k]) >> 8;
        red[t] = s;
    }
    __syncthreads();
    if (t < 10) {
        int s = 0;
        #pragma unroll
        for (int i = 0; i < 8; i++) s += red[t*8 + i];
        vals[t] = (float)s + fb2[t];
    }
    __syncthreads();
    if (t == 0) {
        float m = vals[0];
        #pragma unroll
        for (int i = 1; i < 10; i++) m = fmaxf(m, vals[i]);
        float se = 0.0f;
        #pragma unroll
        for (int i = 0; i < 10; i++) se += expf(vals[i] - m);
        mred[0] = m; mred[1] = logf(se);
    }
    __syncthreads();
    if (t < 10) out[b*10 + t] = vals[t] - mred[0] - mred[1];
}

// ---------------- launch ----------------
extern "C" void kernel_launch(void* const* d_in, const int* in_sizes, int n_in,
                              void* d_out, int out_size) {
    const float* x   = (const float*)d_in[0];
    // d_in[1] = lut — unused: lut[a][b] == (a*b)>>8 exactly
    const float* w1  = (const float*)d_in[2];
    const float* b1  = (const float*)d_in[3];
    const float* w2  = (const float*)d_in[4];
    const float* b2  = (const float*)d_in[5];
    const float* w3  = (const float*)d_in[6];
    const float* b3  = (const float*)d_in[7];
    const float* fw1 = (const float*)d_in[8];
    const float* fb1 = (const float*)d_in[9];
    const float* fw2 = (const float*)d_in[10];
    const float* fb2 = (const float*)d_in[11];
    float* out = (float*)d_out;

    k_max  <<<dim3(32, 6), 256>>>(x, w1, w2, w3, fw1, fw2);
    k_qw   <<<dim3(64, 6), 256>>>(x, w1, w2, w3, fw1, fw2);
    k_conv1<<<256, 392>>>(b1);
    k_conv2<<<256, 784>>>(b2);
    k_conv3<<<512, 448>>>(b3);
    k_fc1  <<<256, 256>>>(fb1);
    k_fc2  <<<32, 128>>>(fb2, out);
}